// round 3
// baseline (speedup 1.0000x reference)
#include <cuda_runtime.h>
#include <cuda_bf16.h>
#include <math.h>

// Problem constants (fixed-shape problem)
#define N_TOK_MAX 11136
#define IN_DIM    256
#define E_DIM     256
#define NHEAD     8
#define HDIM      32
#define NB        16
#define QKV_DIM   768

// QKV layout per reference: reshape(B,S,8,96) then split ->
//   head h: q = cols [96h, 96h+32), k = [96h+32, 96h+64), v = [96h+64, 96h+96)

// Scratch (device globals: allocation-free rule)
__device__ float g_qkv[(size_t)N_TOK_MAX * QKV_DIM];   // [N, 768]
__device__ float g_att[(size_t)N_TOK_MAX * E_DIM];     // [N, 256] attention out
__device__ int   g_start[NB + 1];

// ---------------------------------------------------------------------------
// Kernel 1: histogram of sorted batch ids -> segment start offsets
// ---------------------------------------------------------------------------
__global__ void hist_kernel(const int* __restrict__ ids, int n) {
    __shared__ int cnt[NB];
    int t = threadIdx.x;
    if (t < NB) cnt[t] = 0;
    __syncthreads();
    for (int i = t; i < n; i += blockDim.x)
        atomicAdd(&cnt[ids[i]], 1);
    __syncthreads();
    if (t == 0) {
        int acc = 0;
        for (int v = 0; v < NB; v++) { g_start[v] = acc; acc += cnt[v]; }
        g_start[NB] = acc;
    }
}

// ---------------------------------------------------------------------------
// Tiled SGEMM: C[M,N] = A[M,K] @ B[N,K]^T + bias[N]
// BM=64 BN=64 BK=16, 128 threads, per-thread 8x4 register tile.
// ---------------------------------------------------------------------------
#define BM 64
#define BN 64
#define BK 16

__device__ __forceinline__ void gemm_body(const float* __restrict__ A,
                                          const float* __restrict__ B,
                                          const float* __restrict__ bias,
                                          float* __restrict__ C,
                                          int M, int N, int K) {
    __shared__ float As[BK][BM + 4];
    __shared__ float Bs[BK][BN + 4];
    int t  = threadIdx.x;            // 0..127
    int m0 = blockIdx.y * BM;
    int n0 = blockIdx.x * BN;
    int tn = t & 15;                 // 0..15 -> cols tn*4..+4
    int tm = t >> 4;                 // 0..7  -> rows tm*8..+8

    float acc[8][4];
#pragma unroll
    for (int i = 0; i < 8; i++)
#pragma unroll
        for (int j = 0; j < 4; j++) acc[i][j] = 0.f;

    for (int k0 = 0; k0 < K; k0 += BK) {
        // load A tile (64x16) as float4, store transposed
#pragma unroll
        for (int i = 0; i < 2; i++) {
            int f   = t + i * 128;           // 0..255
            int row = f >> 2, kq = f & 3;
            int gr  = min(m0 + row, M - 1);
            float4 v = *(const float4*)(A + (size_t)gr * K + k0 + kq * 4);
            As[kq * 4 + 0][row] = v.x; As[kq * 4 + 1][row] = v.y;
            As[kq * 4 + 2][row] = v.z; As[kq * 4 + 3][row] = v.w;
        }
        // load B tile (64x16)
#pragma unroll
        for (int i = 0; i < 2; i++) {
            int f   = t + i * 128;
            int row = f >> 2, kq = f & 3;
            float4 v = *(const float4*)(B + (size_t)(n0 + row) * K + k0 + kq * 4);
            Bs[kq * 4 + 0][row] = v.x; Bs[kq * 4 + 1][row] = v.y;
            Bs[kq * 4 + 2][row] = v.z; Bs[kq * 4 + 3][row] = v.w;
        }
        __syncthreads();
#pragma unroll
        for (int k = 0; k < BK; k++) {
            float a[8], b[4];
#pragma unroll
            for (int i = 0; i < 8; i++) a[i] = As[k][tm * 8 + i];
#pragma unroll
            for (int j = 0; j < 4; j++) b[j] = Bs[k][tn * 4 + j];
#pragma unroll
            for (int i = 0; i < 8; i++)
#pragma unroll
                for (int j = 0; j < 4; j++) acc[i][j] += a[i] * b[j];
        }
        __syncthreads();
    }

#pragma unroll
    for (int i = 0; i < 8; i++) {
        int m = m0 + tm * 8 + i;
        if (m < M) {
#pragma unroll
            for (int j = 0; j < 4; j++) {
                int nn = n0 + tn * 4 + j;
                C[(size_t)m * N + nn] = acc[i][j] + bias[nn];
            }
        }
    }
}

__global__ void qkv_gemm_kernel(const float* __restrict__ x,
                                const float* __restrict__ w,
                                const float* __restrict__ b, int n) {
    gemm_body(x, w, b, g_qkv, n, QKV_DIM, IN_DIM);
}

__global__ void proj_gemm_kernel(const float* __restrict__ w,
                                 const float* __restrict__ b,
                                 float* __restrict__ out, int n) {
    gemm_body(g_att, w, b, out, n, E_DIM, E_DIM);
}

// ---------------------------------------------------------------------------
// Kernel 3: varlen flash attention, fp32.
// Block = (32-query chunk of one segment, one head). 128 threads.
// Per-thread 2 rows x 4 cols register tile for QK^T and PV.
// ---------------------------------------------------------------------------
__global__ void attn_kernel(int n) {
    const int seg = blockIdx.y;
    const int h   = blockIdx.z;
    const int qs  = g_start[seg];
    const int qe  = g_start[seg + 1];
    const int q0  = qs + blockIdx.x * 32;
    if (q0 >= qe) return;

    __shared__ float Qs[32][33];
    __shared__ float Ks[32][33];
    __shared__ float Vs[32][33];
    __shared__ float Ss[32][33];

    const int t = threadIdx.x;
    const float* __restrict__ qkv = g_qkv;
    const int qoff = h * 96;        // q cols
    const int koff = h * 96 + 32;   // k cols
    const int voff = h * 96 + 64;   // v cols

    // cooperative Q load: row = t>>2, 8 floats at (t&3)*8
    {
        int r  = t >> 2, c8 = (t & 3) * 8;
        int row = min(q0 + r, n - 1);
        const float* p = qkv + (size_t)row * QKV_DIM + qoff + c8;
#pragma unroll
        for (int c = 0; c < 8; c++) Qs[r][c8 + c] = p[c];
    }
    __syncthreads();

    const int rg = t >> 3;       // 0..15 -> rows {2rg, 2rg+1}
    const int cg = t & 7;        // 0..7  -> cols cg*4..+4
    const int r0 = rg * 2;
    const int c0 = cg * 4;

    float mrow0 = -1e30f, mrow1 = -1e30f;
    float l0 = 0.f, l1 = 0.f;
    float o0[4] = {0, 0, 0, 0}, o1[4] = {0, 0, 0, 0};
    const float scale = 0.17677669529663687f;   // 1/sqrt(32)

    for (int j0 = qs; j0 < qe; j0 += 32) {
        const int nk = min(32, qe - j0);
        // load K,V chunk
        {
            int r  = t >> 2, c8 = (t & 3) * 8;
            int row = min(j0 + r, n - 1);
            const float* kp = qkv + (size_t)row * QKV_DIM + koff + c8;
            const float* vp = qkv + (size_t)row * QKV_DIM + voff + c8;
#pragma unroll
            for (int c = 0; c < 8; c++) Ks[r][c8 + c] = kp[c];
#pragma unroll
            for (int c = 0; c < 8; c++) Vs[r][c8 + c] = vp[c];
        }
        __syncthreads();

        // scores: 2 rows x 4 cols per thread
        float s0[4] = {0, 0, 0, 0}, s1[4] = {0, 0, 0, 0};
#pragma unroll
        for (int k = 0; k < 32; k++) {
            float qv0 = Qs[r0][k];
            float qv1 = Qs[r0 + 1][k];
#pragma unroll
            for (int c = 0; c < 4; c++) {
                float kk = Ks[c0 + c][k];
                s0[c] += qv0 * kk;
                s1[c] += qv1 * kk;
            }
        }
#pragma unroll
        for (int c = 0; c < 4; c++) {
            bool ok = (c0 + c) < nk;
            s0[c] = ok ? s0[c] * scale : -1e30f;
            s1[c] = ok ? s1[c] * scale : -1e30f;
        }

        // chunk row-max (8 threads share a row: xor 1,2,4)
        float mc0 = fmaxf(fmaxf(s0[0], s0[1]), fmaxf(s0[2], s0[3]));
        float mc1 = fmaxf(fmaxf(s1[0], s1[1]), fmaxf(s1[2], s1[3]));
#pragma unroll
        for (int d = 1; d <= 4; d <<= 1) {
            mc0 = fmaxf(mc0, __shfl_xor_sync(0xffffffffu, mc0, d));
            mc1 = fmaxf(mc1, __shfl_xor_sync(0xffffffffu, mc1, d));
        }
        float mn0 = fmaxf(mrow0, mc0);
        float mn1 = fmaxf(mrow1, mc1);
        float sf0 = __expf(mrow0 - mn0);
        float sf1 = __expf(mrow1 - mn1);
        mrow0 = mn0; mrow1 = mn1;

        float ls0 = 0.f, ls1 = 0.f;
#pragma unroll
        for (int c = 0; c < 4; c++) {
            float p0 = __expf(s0[c] - mn0);   // masked -> exp(-1e30) == 0
            float p1 = __expf(s1[c] - mn1);
            ls0 += p0; ls1 += p1;
            Ss[r0][c0 + c]     = p0;
            Ss[r0 + 1][c0 + c] = p1;
        }
#pragma unroll
        for (int d = 1; d <= 4; d <<= 1) {
            ls0 += __shfl_xor_sync(0xffffffffu, ls0, d);
            ls1 += __shfl_xor_sync(0xffffffffu, ls1, d);
        }
        l0 = l0 * sf0 + ls0;
        l1 = l1 * sf1 + ls1;
#pragma unroll
        for (int c = 0; c < 4; c++) { o0[c] *= sf0; o1[c] *= sf1; }
        __syncthreads();   // Ss fully written

        // PV: masked cols have p==0, so full 32-unroll is safe
#pragma unroll
        for (int j = 0; j < 32; j++) {
            float p0 = Ss[r0][j];
            float p1 = Ss[r0 + 1][j];
#pragma unroll
            for (int c = 0; c < 4; c++) {
                float vv = Vs[j][c0 + c];
                o0[c] += p0 * vv;
                o1[c] += p1 * vv;
            }
        }
        __syncthreads();   // before K/V reuse
    }

    float inv0 = 1.0f / l0;
    float inv1 = 1.0f / l1;
    // attention output layout: [N, H*32] (transpose-back in reference)
    if (q0 + r0 < qe) {
        float* p = g_att + (size_t)(q0 + r0) * E_DIM + h * HDIM + c0;
#pragma unroll
        for (int c = 0; c < 4; c++) p[c] = o0[c] * inv0;
    }
    if (q0 + r0 + 1 < qe) {
        float* p = g_att + (size_t)(q0 + r0 + 1) * E_DIM + h * HDIM + c0;
#pragma unroll
        for (int c = 0; c < 4; c++) p[c] = o1[c] * inv1;
    }
}

// ---------------------------------------------------------------------------
extern "C" void kernel_launch(void* const* d_in, const int* in_sizes, int n_in,
                              void* d_out, int out_size) {
    const float* x      = (const float*)d_in[0];
    const int*   ids    = (const int*)  d_in[1];
    const float* qkv_w  = (const float*)d_in[2];
    const float* qkv_b  = (const float*)d_in[3];
    const float* o_w    = (const float*)d_in[4];
    const float* o_b    = (const float*)d_in[5];
    float*       out    = (float*)d_out;
    const int n = in_sizes[1];   // token count

    hist_kernel<<<1, 256>>>(ids, n);

    dim3 g_qkvgrid(QKV_DIM / BN, (n + BM - 1) / BM);
    qkv_gemm_kernel<<<g_qkvgrid, 128>>>(x, qkv_w, qkv_b, n);

    dim3 g_attn((n + 31) / 32, NB, NHEAD);
    attn_kernel<<<g_attn, 128>>>(n);

    dim3 g_proj(E_DIM / BN, (n + BM - 1) / BM);
    proj_gemm_kernel<<<g_proj, 128>>>(o_w, o_b, out, n);
}